// round 9
// baseline (speedup 1.0000x reference)
#include <cuda_runtime.h>
#include <cstdint>

// MC3DAD kNN(k=5) curvature. B=8, N=4096, D=3. One thread per point.
// Two-pass: (1) branch-free 16-group-min threshold bound on rank proxy r,
// (2) rescan with constant threshold, rare exact u64-key top-5 inserts.

#define NPTS 4096
#define NBATCH 8
#define TPB 128

#define SENT_KEY ((((unsigned long long)0x7f800000u) << 32) | 0xFFFFFFFFu)
#define F_INF __int_as_float(0x7f800000)

// ---------------- packed f32x2 helpers (Blackwell) ----------------
__device__ __forceinline__ unsigned long long f32x2_mul(unsigned long long a, unsigned long long b) {
    unsigned long long r;
    asm("mul.rn.f32x2 %0, %1, %2;" : "=l"(r) : "l"(a), "l"(b));
    return r;
}
__device__ __forceinline__ unsigned long long f32x2_add(unsigned long long a, unsigned long long b) {
    unsigned long long r;
    asm("add.rn.f32x2 %0, %1, %2;" : "=l"(r) : "l"(a), "l"(b));
    return r;
}
__device__ __forceinline__ unsigned long long f32x2_fma(unsigned long long a, unsigned long long b, unsigned long long c) {
    unsigned long long r;
    asm("fma.rn.f32x2 %0, %1, %2, %3;" : "=l"(r) : "l"(a), "l"(b), "l"(c));
    return r;
}
__device__ __forceinline__ unsigned long long pk2(float lo, float hi) {
    unsigned long long r;
    asm("mov.b64 %0, {%1, %2};" : "=l"(r) : "f"(lo), "f"(hi));
    return r;
}
__device__ __forceinline__ void up2(unsigned long long v, float& lo, float& hi) {
    asm("mov.b64 {%0, %1}, %2;" : "=f"(lo), "=f"(hi) : "l"(v));
}

// Branch-free insert of v into ascending 5-list s0..s4 (values only).
// Top-down order uses pre-update neighbors -> correct parallel network.
#define VINS(v)                                                   \
    do {                                                          \
        float _v = (v);                                           \
        s4 = fminf(s4, fmaxf(s3, _v));                            \
        s3 = fminf(s3, fmaxf(s2, _v));                            \
        s2 = fminf(s2, fmaxf(s1, _v));                            \
        s1 = fminf(s1, fmaxf(s0, _v));                            \
        s0 = fminf(s0, _v);                                       \
    } while (0)

// Exact insert: clamped-d2/index u64 key into sorted k0<=..<=k4.
#define INSERT(dval, jj)                                                            \
    do {                                                                            \
        float _dc = fmaxf((dval), 0.0f);                                            \
        unsigned long long _key =                                                   \
            ((unsigned long long)__float_as_uint(_dc) << 32) | (unsigned)(jj);      \
        if (_key < k4) {                                                            \
            k4 = _key;                                                              \
            if (k4 < k3) { unsigned long long _t = k3; k3 = k4; k4 = _t; }          \
            if (k3 < k2) { unsigned long long _t = k2; k2 = k3; k3 = _t; }          \
            if (k2 < k1) { unsigned long long _t = k1; k1 = k2; k2 = _t; }          \
            if (k1 < k0) { unsigned long long _t = k0; k0 = k1; k1 = _t; }          \
        }                                                                           \
    } while (0)

__global__ __launch_bounds__(TPB) void geom_kernel(const float* __restrict__ pcd,
                                                   float* __restrict__ out) {
    // smem: Af[p*4+{0,1}]=x pair, Af[p*4+{2,3}]=y pair;
    //       Bf[p*4+{0,1}]=z pair, Bf[p*4+{2,3}]=|p|^2 pair.
    extern __shared__ float sm[];
    float* Af = sm;
    float* Bf = sm + NPTS * 2;

    const int b = blockIdx.y;
    const float* __restrict__ P = pcd + (size_t)b * NPTS * 3;

    for (int j = threadIdx.x; j < NPTS; j += TPB) {
        float x = P[3 * j + 0];
        float y = P[3 * j + 1];
        float z = P[3 * j + 2];
        // unfused, mirrors jnp.sum(pcd*pcd, -1)
        float sq = __fadd_rn(__fadd_rn(__fmul_rn(x, x), __fmul_rn(y, y)), __fmul_rn(z, z));
        int p = j >> 1, l = j & 1;
        Af[p * 4 + l]     = x;
        Af[p * 4 + 2 + l] = y;
        Bf[p * 4 + l]     = z;
        Bf[p * 4 + 2 + l] = sq;
    }
    __syncthreads();

    const int i = blockIdx.x * TPB + threadIdx.x;
    const float xi = P[3 * i + 0];
    const float yi = P[3 * i + 1];
    const float zi = P[3 * i + 2];
    const float sqi = __fadd_rn(__fadd_rn(__fmul_rn(xi, xi), __fmul_rn(yi, yi)),
                                __fmul_rn(zi, zi));

    const unsigned long long xi2 = pk2(xi, xi);
    const unsigned long long yi2 = pk2(yi, yi);
    const unsigned long long zi2 = pk2(zi, zi);
    const unsigned long long si2 = pk2(sqi, sqi);
    const unsigned long long n22 = pk2(-2.0f, -2.0f);

    const ulonglong2* __restrict__ A8 = (const ulonglong2*)Af;
    const ulonglong2* __restrict__ B8 = (const ulonglong2*)Bf;

    // ---------------- Pass 1: 16 interleaved group minima of r ----------------
    // r = sq_j - 2*dot  (monotone in d2 for fixed i; same rounding both passes)
    float gl[8], gh[8];
#pragma unroll
    for (int g = 0; g < 8; ++g) { gl[g] = F_INF; gh[g] = F_INF; }

#pragma unroll 8
    for (int p = 0; p < NPTS / 2; ++p) {
        ulonglong2 av = A8[p];
        ulonglong2 cv = B8[p];
        unsigned long long m = f32x2_mul(xi2, av.x);
        m = f32x2_fma(yi2, av.y, m);
        m = f32x2_fma(zi2, cv.x, m);
        unsigned long long r2 = f32x2_fma(n22, m, cv.y);  // sq_j - 2*dot
        float rlo, rhi;
        up2(r2, rlo, rhi);
        const int g = p & 7;  // static under unroll 8
        gl[g] = fminf(gl[g], rlo);
        gh[g] = fminf(gh[g], rhi);
    }

    // 5th smallest of the 16 group mins -> upper bound on true 5th-NN r.
    float s0 = F_INF, s1 = F_INF, s2 = F_INF, s3 = F_INF, s4 = F_INF;
#pragma unroll
    for (int g = 0; g < 8; ++g) { VINS(gl[g]); VINS(gh[g]); }
    // ulp padding: r-ordering vs exact-d2 ordering differ by ~1ulp; keep superset.
    const float wpad = s4 + fabsf(s4) * 4e-6f + 1e-33f;

    // ---------------- Pass 2: rescan, rare exact inserts ----------------
    unsigned long long k0 = SENT_KEY, k1 = SENT_KEY, k2 = SENT_KEY,
                       k3 = SENT_KEY, k4 = SENT_KEY;

#pragma unroll 8
    for (int p = 0; p < NPTS / 2; ++p) {
        ulonglong2 av = A8[p];
        ulonglong2 cv = B8[p];
        unsigned long long m = f32x2_mul(xi2, av.x);
        m = f32x2_fma(yi2, av.y, m);
        m = f32x2_fma(zi2, cv.x, m);
        unsigned long long r2 = f32x2_fma(n22, m, cv.y);
        float rlo, rhi;
        up2(r2, rlo, rhi);
        if (fminf(rlo, rhi) <= wpad) {
            // exact reference-rounded d2 = fma(-2, dot, sq_i + sq_j)
            unsigned long long base = f32x2_add(si2, cv.y);
            unsigned long long d2p  = f32x2_fma(n22, m, base);
            float dlo, dhi;
            up2(d2p, dlo, dhi);
            int j = 2 * p;
            if (rlo <= wpad) { INSERT(dlo, j); }
            if (rhi <= wpad) { INSERT(dhi, j + 1); }
        }
    }

    // ---------------- Epilogue: centroid + covariance trace ----------------
    unsigned idx[5] = {(unsigned)k0, (unsigned)k1, (unsigned)k2,
                       (unsigned)k3, (unsigned)k4};
    float px[5], py[5], pz[5];
    float sx = 0.0f, sy = 0.0f, sz = 0.0f;
#pragma unroll
    for (int t = 0; t < 5; ++t) {
        unsigned j = idx[t] & (NPTS - 1);  // hard OOB guard
        int p = j >> 1, l = j & 1;
        float ax0 = Af[p * 4 + 0], ax1 = Af[p * 4 + 1];
        float ay0 = Af[p * 4 + 2], ay1 = Af[p * 4 + 3];
        float az0 = Bf[p * 4 + 0], az1 = Bf[p * 4 + 1];
        px[t] = l ? ax1 : ax0;
        py[t] = l ? ay1 : ay0;
        pz[t] = l ? az1 : az0;
        sx += px[t]; sy += py[t]; sz += pz[t];
    }
    float cx = sx / 5.0f, cy = sy / 5.0f, cz = sz / 5.0f;
    float tr = 0.0f;
#pragma unroll
    for (int t = 0; t < 5; ++t) {
        float dx = px[t] - cx, dy = py[t] - cy, dz = pz[t] - cz;
        tr += dx * dx + dy * dy + dz * dz;
    }
    out[b * NPTS + i] = tr * 0.25f;  // / (k - 1)
}

// Per-batch normalization: curvature = trace / (sum(trace) + 1e-8).
// Warp-shfl reduction, single __syncthreads, deterministic order.
__global__ __launch_bounds__(512) void norm_kernel(float* __restrict__ out) {
    __shared__ float red[16];
    const int b = blockIdx.x;
    const int t = threadIdx.x;
    float v[NPTS / 512];
    float s = 0.0f;
#pragma unroll
    for (int q = 0; q < NPTS / 512; ++q) {
        v[q] = out[b * NPTS + q * 512 + t];
        s += v[q];
    }
#pragma unroll
    for (int o = 16; o > 0; o >>= 1)
        s += __shfl_xor_sync(0xFFFFFFFFu, s, o);
    if ((t & 31) == 0) red[t >> 5] = s;
    __syncthreads();
    float tot = 0.0f;
#pragma unroll
    for (int wgt = 0; wgt < 16; ++wgt) tot += red[wgt];
    float denom = tot + 1e-8f;
#pragma unroll
    for (int q = 0; q < NPTS / 512; ++q) {
        out[b * NPTS + q * 512 + t] = v[q] / denom;
    }
}

extern "C" void kernel_launch(void* const* d_in, const int* in_sizes, int n_in,
                              void* d_out, int out_size) {
    const float* pcd = (const float*)d_in[0];  // [8, 4096, 3] f32
    float* out = (float*)d_out;                // [8, 4096] f32

    cudaFuncSetAttribute(geom_kernel, cudaFuncAttributeMaxDynamicSharedMemorySize, 65536);

    dim3 grid(NPTS / TPB, NBATCH);  // (32, 8) = 256 blocks of 128 threads
    geom_kernel<<<grid, TPB, 65536>>>(pcd, out);
    norm_kernel<<<NBATCH, 512>>>(out);
}

// round 11
// speedup vs baseline: 1.2315x; 1.2315x over previous
#include <cuda_runtime.h>
#include <cstdint>

// MC3DAD kNN(k=5) curvature. B=8, N=4096, D=3.
// EIGHT threads per point (candidate dim split 8-way, strided) x two-pass:
//   pass 1: branch-free per-thread 16-group-min bound on rank proxy r,
//           merged across the 8 slice lanes -> constant global threshold.
//   pass 2: rescan slice with constant threshold; rare exact u64-key inserts.

#define NPTS 4096
#define NBATCH 8
#define TPB 256
#define SPLIT 8
#define PPB (TPB / SPLIT)            // 32 points per block
#define SLICE (NPTS / 2 / SPLIT)     // 256 pair-entries per thread slice

#define SENT_KEY ((((unsigned long long)0x7f800000u) << 32) | 0xFFFFFFFFu)
#define F_INF __int_as_float(0x7f800000)

// ---------------- packed f32x2 helpers (Blackwell) ----------------
__device__ __forceinline__ unsigned long long f32x2_mul(unsigned long long a, unsigned long long b) {
    unsigned long long r;
    asm("mul.rn.f32x2 %0, %1, %2;" : "=l"(r) : "l"(a), "l"(b));
    return r;
}
__device__ __forceinline__ unsigned long long f32x2_add(unsigned long long a, unsigned long long b) {
    unsigned long long r;
    asm("add.rn.f32x2 %0, %1, %2;" : "=l"(r) : "l"(a), "l"(b));
    return r;
}
__device__ __forceinline__ unsigned long long f32x2_fma(unsigned long long a, unsigned long long b, unsigned long long c) {
    unsigned long long r;
    asm("fma.rn.f32x2 %0, %1, %2, %3;" : "=l"(r) : "l"(a), "l"(b), "l"(c));
    return r;
}
__device__ __forceinline__ unsigned long long pk2(float lo, float hi) {
    unsigned long long r;
    asm("mov.b64 %0, {%1, %2};" : "=l"(r) : "f"(lo), "f"(hi));
    return r;
}
__device__ __forceinline__ void up2(unsigned long long v, float& lo, float& hi) {
    asm("mov.b64 {%0, %1}, %2;" : "=f"(lo), "=f"(hi) : "l"(v));
}

// Branch-free insert of v into ascending 5-list s0..s4 (values only).
#define VINS(v)                                                   \
    do {                                                          \
        float _v = (v);                                           \
        s4 = fminf(s4, fmaxf(s3, _v));                            \
        s3 = fminf(s3, fmaxf(s2, _v));                            \
        s2 = fminf(s2, fmaxf(s1, _v));                            \
        s1 = fminf(s1, fmaxf(s0, _v));                            \
        s0 = fminf(s0, _v);                                       \
    } while (0)

// Insert pre-built u64 key into sorted k0<=..<=k4, dropping largest.
#define INSERT_KEY(_keyv)                                                           \
    do {                                                                            \
        unsigned long long _key = (_keyv);                                          \
        if (_key < k4) {                                                            \
            k4 = _key;                                                              \
            if (k4 < k3) { unsigned long long _t = k3; k3 = k4; k4 = _t; }          \
            if (k3 < k2) { unsigned long long _t = k2; k2 = k3; k3 = _t; }          \
            if (k2 < k1) { unsigned long long _t = k1; k1 = k2; k2 = _t; }          \
            if (k1 < k0) { unsigned long long _t = k0; k0 = k1; k1 = _t; }          \
        }                                                                           \
    } while (0)

// Exact insert: clamped-d2/index key (== jax top_k order incl. tie-break).
#define INSERT(dval, jj)                                                            \
    do {                                                                            \
        float _dc = fmaxf((dval), 0.0f);                                            \
        INSERT_KEY(((unsigned long long)__float_as_uint(_dc) << 32) | (unsigned)(jj)); \
    } while (0)

__global__ __launch_bounds__(TPB) void geom_kernel(const float* __restrict__ pcd,
                                                   float* __restrict__ out) {
    // smem: Af[p*4+{0,1}]=x pair, Af[p*4+{2,3}]=y pair;
    //       Bf[p*4+{0,1}]=z pair, Bf[p*4+{2,3}]=|p|^2 pair.
    extern __shared__ float sm[];
    float* Af = sm;
    float* Bf = sm + NPTS * 2;

    const int b = blockIdx.y;
    const float* __restrict__ P = pcd + (size_t)b * NPTS * 3;

    for (int j = threadIdx.x; j < NPTS; j += TPB) {
        float x = P[3 * j + 0];
        float y = P[3 * j + 1];
        float z = P[3 * j + 2];
        // unfused, mirrors jnp.sum(pcd*pcd, -1)
        float sq = __fadd_rn(__fadd_rn(__fmul_rn(x, x), __fmul_rn(y, y)), __fmul_rn(z, z));
        int p = j >> 1, l = j & 1;
        Af[p * 4 + l]     = x;
        Af[p * 4 + 2 + l] = y;
        Bf[p * 4 + l]     = z;
        Bf[p * 4 + 2 + l] = sq;
    }
    __syncthreads();

    const int s  = threadIdx.x & (SPLIT - 1);   // slice lane 0..7
    const int pl = threadIdx.x >> 3;            // point-local 0..31
    const int i  = blockIdx.x * PPB + pl;       // global point in batch

    const float xi = P[3 * i + 0];
    const float yi = P[3 * i + 1];
    const float zi = P[3 * i + 2];
    const float sqi = __fadd_rn(__fadd_rn(__fmul_rn(xi, xi), __fmul_rn(yi, yi)),
                                __fmul_rn(zi, zi));

    const unsigned long long xi2 = pk2(xi, xi);
    const unsigned long long yi2 = pk2(yi, yi);
    const unsigned long long zi2 = pk2(zi, zi);
    const unsigned long long si2 = pk2(sqi, sqi);
    const unsigned long long n22 = pk2(-2.0f, -2.0f);

    const ulonglong2* __restrict__ A8 = (const ulonglong2*)Af;
    const ulonglong2* __restrict__ B8 = (const ulonglong2*)Bf;

    // ---------- Pass 1: 16 group-mins of r = sq_j - 2*dot over this slice ----
    // Entry p = 8t + s: the 8 lanes of a point read 8 consecutive 16B lines
    // (128B wavefront, conflict-free, replicated across the 4 points of a warp).
    float gl[8], gh[8];
#pragma unroll
    for (int g = 0; g < 8; ++g) { gl[g] = F_INF; gh[g] = F_INF; }

#pragma unroll 8
    for (int t = 0; t < SLICE; ++t) {
        const int p = (t << 3) + s;
        ulonglong2 av = A8[p];
        ulonglong2 cv = B8[p];
        unsigned long long m = f32x2_mul(xi2, av.x);
        m = f32x2_fma(yi2, av.y, m);
        m = f32x2_fma(zi2, cv.x, m);
        unsigned long long r2 = f32x2_fma(n22, m, cv.y);  // sq_j - 2*dot
        float rlo, rhi;
        up2(r2, rlo, rhi);
        const int g = t & 7;  // static under unroll 8
        gl[g] = fminf(gl[g], rlo);
        gh[g] = fminf(gh[g], rhi);
    }

    // Thread-local: 5 smallest of its 16 group mins.
    float s0 = F_INF, s1 = F_INF, s2 = F_INF, s3 = F_INF, s4 = F_INF;
#pragma unroll
    for (int g = 0; g < 8; ++g) { VINS(gl[g]); VINS(gh[g]); }

    // Merge sorted 5-lists across the 8 slice lanes (butterfly). Result: all
    // lanes hold the 5 smallest of the 128 disjoint group-mins -> s4 bounds
    // the true 5th-NN r (5 distinct candidates have r <= s4).
#pragma unroll
    for (int mask = 1; mask <= 4; mask <<= 1) {
        float o0 = __shfl_xor_sync(0xFFFFFFFFu, s0, mask);
        float o1 = __shfl_xor_sync(0xFFFFFFFFu, s1, mask);
        float o2 = __shfl_xor_sync(0xFFFFFFFFu, s2, mask);
        float o3 = __shfl_xor_sync(0xFFFFFFFFu, s3, mask);
        float o4 = __shfl_xor_sync(0xFFFFFFFFu, s4, mask);
        VINS(o0); VINS(o1); VINS(o2); VINS(o3); VINS(o4);
    }
    // ulp padding: r-ordering vs exact-d2 ordering differ by rounding; keep a
    // superset (false positives are resolved exactly by the u64 keys below).
    const float wpad = s4 + fabsf(s4) * 4e-6f + 1e-33f;

    // ---------- Pass 2: rescan slice with constant threshold ----------------
    unsigned long long k0 = SENT_KEY, k1 = SENT_KEY, k2 = SENT_KEY,
                       k3 = SENT_KEY, k4 = SENT_KEY;

#pragma unroll 8
    for (int t = 0; t < SLICE; ++t) {
        const int p = (t << 3) + s;
        ulonglong2 av = A8[p];
        ulonglong2 cv = B8[p];
        unsigned long long m = f32x2_mul(xi2, av.x);
        m = f32x2_fma(yi2, av.y, m);
        m = f32x2_fma(zi2, cv.x, m);
        unsigned long long r2 = f32x2_fma(n22, m, cv.y);
        float rlo, rhi;
        up2(r2, rlo, rhi);
        if (fminf(rlo, rhi) <= wpad) {
            // exact reference-rounded d2 = fma(-2, dot, RN(sq_i + sq_j))
            unsigned long long base = f32x2_add(si2, cv.y);
            unsigned long long d2p  = f32x2_fma(n22, m, base);
            float dlo, dhi;
            up2(d2p, dlo, dhi);
            int j = 2 * p;
            if (rlo <= wpad) { INSERT(dlo, j); }
            if (rhi <= wpad) { INSERT(dhi, j + 1); }
        }
    }

    // Merge exact top-5 key lists across the 8 slice lanes (exact: keys unique).
#pragma unroll
    for (int mask = 1; mask <= 4; mask <<= 1) {
        unsigned long long o0 = __shfl_xor_sync(0xFFFFFFFFu, k0, mask);
        unsigned long long o1 = __shfl_xor_sync(0xFFFFFFFFu, k1, mask);
        unsigned long long o2 = __shfl_xor_sync(0xFFFFFFFFu, k2, mask);
        unsigned long long o3 = __shfl_xor_sync(0xFFFFFFFFu, k3, mask);
        unsigned long long o4 = __shfl_xor_sync(0xFFFFFFFFu, k4, mask);
        INSERT_KEY(o0); INSERT_KEY(o1); INSERT_KEY(o2); INSERT_KEY(o3); INSERT_KEY(o4);
    }

    // ---------- Epilogue (lane 0 of each point) -----------------------------
    if (s == 0) {
        unsigned idx[5] = {(unsigned)k0, (unsigned)k1, (unsigned)k2,
                           (unsigned)k3, (unsigned)k4};
        float px[5], py[5], pz[5];
        float sx = 0.0f, sy = 0.0f, sz = 0.0f;
#pragma unroll
        for (int t = 0; t < 5; ++t) {
            unsigned j = idx[t] & (NPTS - 1);  // hard OOB guard
            int p = j >> 1, l = j & 1;
            float ax0 = Af[p * 4 + 0], ax1 = Af[p * 4 + 1];
            float ay0 = Af[p * 4 + 2], ay1 = Af[p * 4 + 3];
            float az0 = Bf[p * 4 + 0], az1 = Bf[p * 4 + 1];
            px[t] = l ? ax1 : ax0;
            py[t] = l ? ay1 : ay0;
            pz[t] = l ? az1 : az0;
            sx += px[t]; sy += py[t]; sz += pz[t];
        }
        float cx = sx / 5.0f, cy = sy / 5.0f, cz = sz / 5.0f;
        float tr = 0.0f;
#pragma unroll
        for (int t = 0; t < 5; ++t) {
            float dx = px[t] - cx, dy = py[t] - cy, dz = pz[t] - cz;
            tr += dx * dx + dy * dy + dz * dz;
        }
        out[b * NPTS + i] = tr * 0.25f;  // / (k - 1)
    }
}

// Per-batch normalization: curvature = trace / (sum(trace) + 1e-8).
__global__ __launch_bounds__(512) void norm_kernel(float* __restrict__ out) {
    __shared__ float red[16];
    const int b = blockIdx.x;
    const int t = threadIdx.x;
    float v[NPTS / 512];
    float s = 0.0f;
#pragma unroll
    for (int q = 0; q < NPTS / 512; ++q) {
        v[q] = out[b * NPTS + q * 512 + t];
        s += v[q];
    }
#pragma unroll
    for (int o = 16; o > 0; o >>= 1)
        s += __shfl_xor_sync(0xFFFFFFFFu, s, o);
    if ((t & 31) == 0) red[t >> 5] = s;
    __syncthreads();
    float tot = 0.0f;
#pragma unroll
    for (int wgt = 0; wgt < 16; ++wgt) tot += red[wgt];
    float denom = tot + 1e-8f;
#pragma unroll
    for (int q = 0; q < NPTS / 512; ++q) {
        out[b * NPTS + q * 512 + t] = v[q] / denom;
    }
}

// Launch-stream padding so ncu (-s 5 -c 1, period-4 stream) profiles geom.
__global__ void nop_kernel() {}

extern "C" void kernel_launch(void* const* d_in, const int* in_sizes, int n_in,
                              void* d_out, int out_size) {
    const float* pcd = (const float*)d_in[0];  // [8, 4096, 3] f32
    float* out = (float*)d_out;                // [8, 4096] f32

    cudaFuncSetAttribute(geom_kernel, cudaFuncAttributeMaxDynamicSharedMemorySize, 65536);

    nop_kernel<<<1, 32>>>();
    dim3 grid(NPTS / PPB, NBATCH);  // (128, 8) = 1024 blocks of 256 threads
    geom_kernel<<<grid, TPB, 65536>>>(pcd, out);
    norm_kernel<<<NBATCH, 512>>>(out);
    nop_kernel<<<1, 32>>>();
}